// round 5
// baseline (speedup 1.0000x reference)
#include <cuda_runtime.h>
#include <cuda_fp16.h>
#include <math.h>

#define C 32
#define LAYERS 4
#define NFIX 2
#define MAXN 100000
#define MAXE 1600000
#define LC (LAYERS * C)   // 128
#define CAP 96            // per-node edge bucket capacity (deg ~ Poisson(16))

typedef unsigned long long u64;

// ---------------- device scratch (no runtime allocation allowed) -----------
__device__ __align__(256) __half g_dZ[(size_t)MAXN * LC];        // [N][L][C] fp16
__device__ __align__(256) float  g_Z[(size_t)LAYERS * MAXN * C]; // [L][N][C]
__device__ __align__(16)  uint2  g_rec[(size_t)MAXN * CAP];      // bucketed (t, w)
__device__ int g_cnt[MAXN];

// ---------------- helpers ---------------------------------------------------
__device__ __forceinline__ float silu_f(float x) {
    // silu(x) = hx + hx*tanh(hx), hx = x/2   (1 MUFU)
    float t;
    asm("tanh.approx.f32 %0, %1;" : "=f"(t) : "f"(0.5f * x));
    float hx = 0.5f * x;
    return fmaf(hx, t, hx);
}
__device__ __forceinline__ u64 pack2(float a, float b) {
    u64 r; asm("mov.b64 %0, {%1, %2};" : "=l"(r) : "f"(a), "f"(b)); return r;
}
__device__ __forceinline__ void unpack2(u64 v, float& a, float& b) {
    asm("mov.b64 {%0, %1}, %2;" : "=f"(a), "=f"(b) : "l"(v));
}
__device__ __forceinline__ u64 fma2(u64 a, u64 b, u64 c) {
    u64 d; asm("fma.rn.f32x2 %0, %1, %2, %3;" : "=l"(d) : "l"(a), "l"(b), "l"(c));
    return d;
}

// ---------------- bucketed CSR build ----------------------------------------
__global__ void zero_cnt_kernel(int* cnt, int N) {
    int i = blockIdx.x * blockDim.x + threadIdx.x;
    if (i < N) cnt[i] = 0;
}

__global__ void scatter_kernel(const int* __restrict__ ei, const float* __restrict__ ew,
                               int* cnt, uint2* rec, int E) {
    int e = blockIdx.x * blockDim.x + threadIdx.x;
    if (e >= E) return;
    int s = __ldg(ei + e);
    int t = __ldg(ei + E + e);
    float w = __ldg(ew + e);
    int p = atomicAdd(&cnt[s], 1);
    if (p < CAP) rec[(size_t)s * CAP + p] = make_uint2((unsigned)t, __float_as_uint(w));
}

// ---------------------------------------------------------------------------
// Node forward: per (node, layer): h = silu([Z_l, f] @ Kf_l); dZ = h @ K_l
// Packed f32x2 FMA; SMEM weights read as ulonglong2. dZ fp16 node-major.
// ---------------------------------------------------------------------------
__global__ __launch_bounds__(256) void node_forward_kernel(
        const float* __restrict__ Z,
        const float* __restrict__ f,
        const float* __restrict__ Kf,
        const float* __restrict__ K,
        __half* __restrict__ dZ,
        int N, int useZ)
{
    __shared__ __align__(16) float Kfs[2 * C * C];   // 8 KB
    __shared__ __align__(16) float Ks[C * C];        // 4 KB
    const int l = blockIdx.y;
    {
        const float4* Kfl = (const float4*)(Kf + (size_t)l * 2 * C * C);
        const float4* Kl  = (const float4*)(K  + (size_t)l * C * C);
        float4* s0 = (float4*)Kfs;
        float4* s1 = (float4*)Ks;
        for (int i = threadIdx.x; i < 2 * C * C / 4; i += blockDim.x) s0[i] = Kfl[i];
        for (int i = threadIdx.x; i < C * C / 4;     i += blockDim.x) s1[i] = Kl[i];
    }
    __syncthreads();

    const int n = blockIdx.x * blockDim.x + threadIdx.x;
    if (n >= N) return;

    u64 hp[16];
#pragma unroll
    for (int i = 0; i < 16; i++) hp[i] = 0ULL;

    if (useZ) {
        const float4* zr = (const float4*)(Z + ((size_t)l * N + n) * C);
#pragma unroll
        for (int k4 = 0; k4 < 8; k4++) {
            float4 zv = zr[k4];
            float zs[4] = {zv.x, zv.y, zv.z, zv.w};
#pragma unroll
            for (int kk = 0; kk < 4; kk++) {
                u64 s2 = pack2(zs[kk], zs[kk]);
                const ulonglong2* wr = (const ulonglong2*)&Kfs[(k4 * 4 + kk) * C];
#pragma unroll
                for (int c4 = 0; c4 < 8; c4++) {
                    ulonglong2 w = wr[c4];
                    hp[2 * c4 + 0] = fma2(s2, w.x, hp[2 * c4 + 0]);
                    hp[2 * c4 + 1] = fma2(s2, w.y, hp[2 * c4 + 1]);
                }
            }
        }
    }
    {
        const float4* fr = (const float4*)(f + (size_t)n * C);
#pragma unroll
        for (int k4 = 0; k4 < 8; k4++) {
            float4 fv = fr[k4];
            float fs[4] = {fv.x, fv.y, fv.z, fv.w};
#pragma unroll
            for (int kk = 0; kk < 4; kk++) {
                u64 s2 = pack2(fs[kk], fs[kk]);
                const ulonglong2* wr = (const ulonglong2*)&Kfs[(C + k4 * 4 + kk) * C];
#pragma unroll
                for (int c4 = 0; c4 < 8; c4++) {
                    ulonglong2 w = wr[c4];
                    hp[2 * c4 + 0] = fma2(s2, w.x, hp[2 * c4 + 0]);
                    hp[2 * c4 + 1] = fma2(s2, w.y, hp[2 * c4 + 1]);
                }
            }
        }
    }

    float h[C];
#pragma unroll
    for (int i = 0; i < 16; i++) unpack2(hp[i], h[2 * i], h[2 * i + 1]);
#pragma unroll
    for (int c = 0; c < C; c++) h[c] = silu_f(h[c]);

    u64 dp[16];
#pragma unroll
    for (int i = 0; i < 16; i++) dp[i] = 0ULL;
#pragma unroll
    for (int k = 0; k < C; k++) {
        u64 s2 = pack2(h[k], h[k]);
        const ulonglong2* wr = (const ulonglong2*)&Ks[k * C];
#pragma unroll
        for (int c4 = 0; c4 < 8; c4++) {
            ulonglong2 w = wr[c4];
            dp[2 * c4 + 0] = fma2(s2, w.x, dp[2 * c4 + 0]);
            dp[2 * c4 + 1] = fma2(s2, w.y, dp[2 * c4 + 1]);
        }
    }

    union { __half2 h2[16]; uint4 u[4]; } pk;
#pragma unroll
    for (int i = 0; i < 16; i++) {
        float x, y;
        unpack2(dp[i], x, y);
        pk.h2[i] = __float22half2_rn(make_float2(x, y));
    }
    uint4* dzp = (uint4*)(dZ + ((size_t)n * LAYERS + l) * C);
#pragma unroll
    for (int q = 0; q < 4; q++) dzp[q] = pk.u[q];
}

// ---------------------------------------------------------------------------
// Fused: CSR-bucket gather (f32 silu math on fp16 rows) + Y = -(agg @ K^T)
// (+X) + tridiag + Z store. Warp per node; grid-stride; 32 warps/SM.
// ---------------------------------------------------------------------------
__device__ __forceinline__ void edge_accum(uint2 zb,
                                           float a0, float a1, float a2, float a3,
                                           float w,
                                           float& acc0, float& acc1,
                                           float& acc2, float& acc3)
{
    float2 b01 = __half22float2(*(const __half2*)&zb.x);
    float2 b23 = __half22float2(*(const __half2*)&zb.y);
    acc0 += silu_f(w * (a0 - b01.x));
    acc1 += silu_f(w * (a1 - b01.y));
    acc2 += silu_f(w * (a2 - b23.x));
    acc3 += silu_f(w * (a3 - b23.y));
}

__global__ __launch_bounds__(256, 4) void edge_tri_kernel(
        const __half* __restrict__ dZ,
        const uint2* __restrict__ rec,
        const int* __restrict__ cnt,
        const float* __restrict__ K,
        const float* __restrict__ X,
        float* __restrict__ Zout,
        float* __restrict__ lastOut,
        int N)
{
    __shared__ __align__(16) float KT[LAYERS * C * C];   // 16 KB
    __shared__ __align__(16) float sY[8][LC];            // 4 KB
    for (int i = threadIdx.x; i < LAYERS * C * C; i += blockDim.x) {
        int l = i >> 10;
        int c = (i >> 5) & 31;
        int j = i & 31;
        KT[(l * C + j) * C + c] = K[i];
    }
    __syncthreads();

    const int lane = threadIdx.x & 31;
    const int warp = threadIdx.x >> 5;
    const int gwarp = blockIdx.x * 8 + warp;
    const int nwarps = gridDim.x * 8;
    const int l = lane >> 3;
    const int cBase = (lane & 7) * 4;
    const size_t NC = (size_t)N * C;

    for (int n = gwarp; n < N; n += nwarps) {
        uint2 za = __ldg((const uint2*)(dZ + (size_t)n * LC) + lane);
        float2 a01 = __half22float2(*(const __half2*)&za.x);
        float2 a23 = __half22float2(*(const __half2*)&za.y);
        const float a0 = a01.x, a1 = a01.y, a2 = a23.x, a3 = a23.y;

        float acc0 = 0.f, acc1 = 0.f, acc2 = 0.f, acc3 = 0.f;
        int deg = __ldg(cnt + n);
        if (deg > CAP) deg = CAP;
        const uint2* row = rec + (size_t)n * CAP;

        int p = 0;
        for (; p + 4 <= deg; p += 4) {
            uint2 r0 = __ldg(row + p + 0);
            uint2 r1 = __ldg(row + p + 1);
            uint2 r2 = __ldg(row + p + 2);
            uint2 r3 = __ldg(row + p + 3);
            uint2 z0 = __ldg((const uint2*)(dZ + (size_t)r0.x * LC) + lane);
            uint2 z1 = __ldg((const uint2*)(dZ + (size_t)r1.x * LC) + lane);
            uint2 z2 = __ldg((const uint2*)(dZ + (size_t)r2.x * LC) + lane);
            uint2 z3 = __ldg((const uint2*)(dZ + (size_t)r3.x * LC) + lane);
            edge_accum(z0, a0, a1, a2, a3, __uint_as_float(r0.y), acc0, acc1, acc2, acc3);
            edge_accum(z1, a0, a1, a2, a3, __uint_as_float(r1.y), acc0, acc1, acc2, acc3);
            edge_accum(z2, a0, a1, a2, a3, __uint_as_float(r2.y), acc0, acc1, acc2, acc3);
            edge_accum(z3, a0, a1, a2, a3, __uint_as_float(r3.y), acc0, acc1, acc2, acc3);
        }
        for (; p < deg; p++) {
            uint2 r0 = __ldg(row + p);
            uint2 z0 = __ldg((const uint2*)(dZ + (size_t)r0.x * LC) + lane);
            edge_accum(z0, a0, a1, a2, a3, __uint_as_float(r0.y), acc0, acc1, acc2, acc3);
        }

        // matvec: y[c] = sum_j acc[l][j] * KT[l][j][c]  (negated into sY)
        float av[4] = {acc0, acc1, acc2, acc3};
        u64 y01 = 0ULL, y23 = 0ULL;
#pragma unroll
        for (int j = 0; j < C; j++) {
            int src = (lane & 248) | (j >> 2);
            float bv = __shfl_sync(0xffffffffu, av[j & 3], src);
            u64 b2 = pack2(bv, bv);
            ulonglong2 w = *(const ulonglong2*)&KT[(l * C + j) * C + cBase];
            y01 = fma2(b2, w.x, y01);
            y23 = fma2(b2, w.y, y23);
        }
        float y0, y1, y2, y3;
        unpack2(y01, y0, y1);
        unpack2(y23, y2, y3);
        *(float4*)&sY[warp][lane * 4] = make_float4(-y0, -y1, -y2, -y3);
        __syncwarp();

        float Y0 = sY[warp][0 * C + lane];
        float Y1 = sY[warp][1 * C + lane];
        float Y2 = sY[warp][2 * C + lane];
        float Y3 = sY[warp][3 * C + lane] + __ldg(X + (size_t)n * C + lane);

        const float s12 = 0.70710678118654752f;
        const float s23v = 0.81649658092772603f;
        const float s34 = 0.86602540378443865f;
        const float s45 = 0.89442719099991588f;
        float t0 = s12 * Y0;
        float t1 = s23v * (s12 * t0 + Y1);
        float t2 = s34 * (s23v * t1 + Y2);
        float t3 = s45 * (s34 * t2 + Y3);
        float w3 = s45 * t3;
        float w2 = s34 * (s34 * w3 + t2);
        float w1 = s23v * (s23v * w2 + t1);
        float w0 = s12 * (s12 * w1 + t0);

        const size_t base = (size_t)n * C + lane;
        Zout[0 * NC + base] = w0;
        Zout[1 * NC + base] = w1;
        Zout[2 * NC + base] = w2;
        Zout[3 * NC + base] = w3;
        if (lastOut) lastOut[base] = w3;
        __syncwarp();   // sY reuse
    }
}

// ---------------------------------------------------------------------------
extern "C" void kernel_launch(void* const* d_in, const int* in_sizes, int n_in,
                              void* d_out, int out_size)
{
    const float* X  = (const float*)d_in[0];
    const float* f  = (const float*)d_in[1];
    const int*   ei = (const int*)d_in[2];
    const float* ew = (const float*)d_in[3];
    const float* K  = (const float*)d_in[4];
    const float* Kf = (const float*)d_in[5];

    const int N = in_sizes[0] / C;
    const int E = in_sizes[3];

    __half* dZ; float* Zb; uint2* rec; int* cnt;
    cudaGetSymbolAddress((void**)&dZ,  g_dZ);
    cudaGetSymbolAddress((void**)&Zb,  g_Z);
    cudaGetSymbolAddress((void**)&rec, g_rec);
    cudaGetSymbolAddress((void**)&cnt, g_cnt);

    const size_t NC = (size_t)N * C;
    float* out = (float*)d_out;
    float* Zfinal;
    float* lastPtr;
    if ((size_t)out_size >= (size_t)(LAYERS + 1) * NC) {
        lastPtr = out;            // Z[-1] first
        Zfinal  = out + NC;       // then full Z
    } else if ((size_t)out_size >= (size_t)LAYERS * NC) {
        Zfinal  = out;
        lastPtr = nullptr;
    } else {
        Zfinal  = Zb;
        lastPtr = out;
    }

    zero_cnt_kernel<<<(N + 511) / 512, 512>>>(cnt, N);
    scatter_kernel<<<(E + 511) / 512, 512>>>(ei, ew, cnt, rec, E);

    dim3 nodeGrid((N + 255) / 256, LAYERS);
    const int fusedBlocks = 592;   // 4 per SM, 8 warps each

    for (int it = 0; it < NFIX; it++) {
        node_forward_kernel<<<nodeGrid, 256>>>(Zb, f, Kf, K, dZ, N, it > 0 ? 1 : 0);
        const bool last = (it == NFIX - 1);
        edge_tri_kernel<<<fusedBlocks, 256>>>(dZ, rec, cnt, K, X,
                                              last ? Zfinal : Zb,
                                              last ? lastPtr : nullptr,
                                              N);
    }
}